// round 15
// baseline (speedup 1.0000x reference)
#include <cuda_runtime.h>
#include <math.h>
#include <cstdint>

#define B_  8
#define T_  1024
#define D_  1024
#define H_  16
#define DH_ 64
#define M_  (B_*T_)     // 8192
#define N3_ (3*D_)      // 3072
#define HALF_D 512

// ---------------- scratch -------------------------------------------------------
__device__ __align__(1024) float g_xn[(size_t)M_*D_];
__device__ __align__(1024) float g_qkv[(size_t)M_*N3_];
__device__ __align__(1024) float g_attn[(size_t)M_*D_];
__device__ float g_sin[T_*HALF_D];      // [t][pair]
__device__ float g_cos[T_*HALF_D];
__device__ int   g_len[B_];
__device__ int   g_flag_q;              // 1 -> gemm16 qkv wrong -> fallback
__device__ int   g_flag_o;              // 1 -> gemm16 out wrong -> fallback

// ---------------- fast exp on the FMA pipe, x <= 0 (validated) ------------------
__device__ __forceinline__ float fexp(float x) {
    x = fmaxf(x, -87.0f);
    const float y = x * 1.4426950408889634f;         // x * log2(e)
    const float n = rintf(y);
    const float t = (y - n) * 0.6931471805599453f;   // |t| <= 0.3466
    float p = fmaf(t, 1.0f/120.0f, 1.0f/24.0f);
    p = fmaf(t, p, 1.0f/6.0f);
    p = fmaf(t, p, 0.5f);
    p = fmaf(t, p, 1.0f);
    p = fmaf(t, p, 1.0f);
    const int e = (int)n;
    return p * __int_as_float((e + 127) << 23);
}

// ---------------- layernorm (round-1 exact) -------------------------------------
__global__ void __launch_bounds__(256) ln_kernel(const float* __restrict__ x,
                                                 const float* __restrict__ gamma,
                                                 const float* __restrict__ beta) {
    __shared__ float ssum[8], ssq[8];
    const int row = blockIdx.x;
    const int tid = threadIdx.x;
    float4 v = *(const float4*)(x + (size_t)row * D_ + tid * 4);
    float s = v.x + v.y + v.z + v.w;
    float q = v.x*v.x + v.y*v.y + v.z*v.z + v.w*v.w;
    #pragma unroll
    for (int o = 16; o > 0; o >>= 1) {
        s += __shfl_down_sync(0xffffffffu, s, o);
        q += __shfl_down_sync(0xffffffffu, q, o);
    }
    if ((tid & 31) == 0) { ssum[tid >> 5] = s; ssq[tid >> 5] = q; }
    __syncthreads();
    float ts = 0.f, tq = 0.f;
    #pragma unroll
    for (int i = 0; i < 8; i++) { ts += ssum[i]; tq += ssq[i]; }
    const float mu  = ts * (1.f / 1024.f);
    const float var = tq * (1.f / 1024.f) - mu * mu;
    const float inv = rsqrtf(var + 1e-5f);
    float4 g  = *(const float4*)(gamma + tid * 4);
    float4 be = *(const float4*)(beta  + tid * 4);
    float4 out;
    out.x = (v.x - mu) * inv * g.x + be.x;
    out.y = (v.y - mu) * inv * g.y + be.y;
    out.z = (v.z - mu) * inv * g.z + be.z;
    out.w = (v.w - mu) * inv * g.w + be.w;
    *(float4*)(g_xn + (size_t)row * D_ + tid * 4) = out;
}

// ---------------- rope tables (round-1 exact) ------------------------------------
__global__ void rope_table_kernel() {
    const int idx = blockIdx.x * blockDim.x + threadIdx.x;
    if (idx >= T_ * HALF_D) return;
    const int t = idx >> 9;
    const int i = idx & (HALF_D - 1);
    const float e   = -(((float)i - 1.0f) * (1.0f / 512.0f));
    const float inv = expf(e * 11.512925464970229f);   // ln(1e5)
    float sn, cs;
    sincosf((float)t * inv, &sn, &cs);
    g_sin[idx] = sn;
    g_cos[idx] = cs;
}

// ---------------- sequence lengths (round-1 exact) --------------------------------
__global__ void len_kernel(const unsigned int* __restrict__ mask) {
    __shared__ int sc[8];
    const int b = blockIdx.x, tid = threadIdx.x;
    int c = 0;
    for (int i = tid; i < T_; i += 256) c += (mask[b * T_ + i] != 0u);
    #pragma unroll
    for (int o = 16; o > 0; o >>= 1) c += __shfl_down_sync(0xffffffffu, c, o);
    if ((tid & 31) == 0) sc[tid >> 5] = c;
    __syncthreads();
    if (tid == 0) {
        int t = 0;
        #pragma unroll
        for (int i = 0; i < 8; i++) t += sc[i];
        g_len[b] = t;
    }
}

// ---------------- SGEMM, K-chunk 16 (FIXED in-bounds loader) ----------------------
// A: thread -> row tid>>1 (0..127), k-cols ac8..ac8+7 (ac8 in {0,8})   -> 2048 ok
// B: thread -> k-row tid>>4 (0..15), n-cols bc8..bc8+7 (bc8 = (tid&15)*8) -> 2048 ok
template<int N, bool ROPE>
__global__ void __launch_bounds__(256) gemm16(const float* __restrict__ A,
                                              const float* __restrict__ Bm,
                                              const float* __restrict__ bias,
                                              float* __restrict__ C) {
    __shared__ float As[16][128];
    __shared__ float Bs[16][128];
    const int tid = threadIdx.x;
    const int bm = blockIdx.y, bn = blockIdx.x;
    const int arow = tid >> 1, ac8 = (tid & 1) << 3;
    const int brow = tid >> 4, bc8 = (tid & 15) << 3;
    const int tx = tid & 15, ty = tid >> 4;

    const float* Ap = A + (size_t)(bm * 128 + arow) * 1024 + ac8;
    const float* Bp = Bm + (size_t)brow * N + bn * 128 + bc8;

    float acc[8][8];
    #pragma unroll
    for (int i = 0; i < 8; i++)
        #pragma unroll
        for (int j = 0; j < 8; j++) acc[i][j] = 0.f;

    for (int k0 = 0; k0 < 1024; k0 += 16) {
        float4 a4 = *(const float4*)(Ap + k0);
        float4 a5 = *(const float4*)(Ap + k0 + 4);
        float4 b4 = *(const float4*)(Bp + (size_t)k0 * N);
        float4 b5 = *(const float4*)(Bp + (size_t)k0 * N + 4);
        As[ac8 + 0][arow] = a4.x;
        As[ac8 + 1][arow] = a4.y;
        As[ac8 + 2][arow] = a4.z;
        As[ac8 + 3][arow] = a4.w;
        As[ac8 + 4][arow] = a5.x;
        As[ac8 + 5][arow] = a5.y;
        As[ac8 + 6][arow] = a5.z;
        As[ac8 + 7][arow] = a5.w;
        *(float4*)(&Bs[brow][bc8])     = b4;
        *(float4*)(&Bs[brow][bc8 + 4]) = b5;
        __syncthreads();
        #pragma unroll
        for (int kk = 0; kk < 16; kk++) {
            float4 a0 = *(const float4*)(&As[kk][ty * 8]);
            float4 a1 = *(const float4*)(&As[kk][ty * 8 + 4]);
            float4 b0 = *(const float4*)(&Bs[kk][tx * 8]);
            float4 b1 = *(const float4*)(&Bs[kk][tx * 8 + 4]);
            float ar[8] = {a0.x, a0.y, a0.z, a0.w, a1.x, a1.y, a1.z, a1.w};
            float br[8] = {b0.x, b0.y, b0.z, b0.w, b1.x, b1.y, b1.z, b1.w};
            #pragma unroll
            for (int i = 0; i < 8; i++)
                #pragma unroll
                for (int j = 0; j < 8; j++)
                    acc[i][j] = fmaf(ar[i], br[j], acc[i][j]);
        }
        __syncthreads();
    }

    const int row0 = bm * 128 + ty * 8;
    const int col0 = bn * 128 + tx * 8;
    #pragma unroll
    for (int i = 0; i < 8; i++) {
        const int r = row0 + i;
        if (ROPE) {
            const int t = r & (T_ - 1);
            #pragma unroll
            for (int j = 0; j < 8; j += 2) {
                const int c  = col0 + j;
                const int pi = (c & (D_ - 1)) >> 1;
                const float sn = g_sin[t * HALF_D + pi];
                const float cs = g_cos[t * HALF_D + pi];
                const float e = acc[i][j]     + bias[c];
                const float o = acc[i][j + 1] + bias[c + 1];
                acc[i][j]     = fmaf(e, cs, -o * sn);
                acc[i][j + 1] = fmaf(o, cs,  e * sn);
            }
        } else {
            #pragma unroll
            for (int j = 0; j < 8; j++) acc[i][j] += bias[col0 + j];
        }
        float4* out = (float4*)(C + (size_t)r * N + col0);
        out[0] = make_float4(acc[i][0], acc[i][1], acc[i][2], acc[i][3]);
        out[1] = make_float4(acc[i][4], acc[i][5], acc[i][6], acc[i][7]);
    }
}

// ---------------- round-1 SGEMM body (trusted, FROZEN fallback) -------------------
template<int N, bool ROPE>
__device__ __forceinline__ void gemm_body(const float* __restrict__ A,
                                          const float* __restrict__ Bm,
                                          const float* __restrict__ bias,
                                          float* __restrict__ C) {
    __shared__ float As[8][128];
    __shared__ float Bs[8][128];
    const int tid = threadIdx.x;
    const int bm = blockIdx.y, bn = blockIdx.x;
    const int arow = tid >> 1, acol = (tid & 1) << 2;
    const int brow = tid >> 5, bcol = (tid & 31) << 2;
    const int tx = tid & 15, ty = tid >> 4;

    const float* Ap = A + (size_t)(bm * 128 + arow) * 1024 + acol;
    const float* Bp = Bm + (size_t)brow * N + bn * 128 + bcol;

    float acc[8][8];
    #pragma unroll
    for (int i = 0; i < 8; i++)
        #pragma unroll
        for (int j = 0; j < 8; j++) acc[i][j] = 0.f;

    for (int k0 = 0; k0 < 1024; k0 += 8) {
        float4 a4 = *(const float4*)(Ap + k0);
        float4 b4 = *(const float4*)(Bp + (size_t)k0 * N);
        As[acol + 0][arow] = a4.x;
        As[acol + 1][arow] = a4.y;
        As[acol + 2][arow] = a4.z;
        As[acol + 3][arow] = a4.w;
        *(float4*)(&Bs[brow][bcol]) = b4;
        __syncthreads();
        #pragma unroll
        for (int kk = 0; kk < 8; kk++) {
            float4 a0 = *(const float4*)(&As[kk][ty * 8]);
            float4 a1 = *(const float4*)(&As[kk][ty * 8 + 4]);
            float4 b0 = *(const float4*)(&Bs[kk][tx * 8]);
            float4 b1 = *(const float4*)(&Bs[kk][tx * 8 + 4]);
            float ar[8] = {a0.x, a0.y, a0.z, a0.w, a1.x, a1.y, a1.z, a1.w};
            float br[8] = {b0.x, b0.y, b0.z, b0.w, b1.x, b1.y, b1.z, b1.w};
            #pragma unroll
            for (int i = 0; i < 8; i++)
                #pragma unroll
                for (int j = 0; j < 8; j++)
                    acc[i][j] = fmaf(ar[i], br[j], acc[i][j]);
        }
        __syncthreads();
    }

    const int row0 = bm * 128 + ty * 8;
    const int col0 = bn * 128 + tx * 8;
    #pragma unroll
    for (int i = 0; i < 8; i++) {
        const int r = row0 + i;
        if (ROPE) {
            const int t = r & (T_ - 1);
            #pragma unroll
            for (int j = 0; j < 8; j += 2) {
                const int c  = col0 + j;
                const int pi = (c & (D_ - 1)) >> 1;
                const float sn = g_sin[t * HALF_D + pi];
                const float cs = g_cos[t * HALF_D + pi];
                const float e = acc[i][j]     + bias[c];
                const float o = acc[i][j + 1] + bias[c + 1];
                acc[i][j]     = fmaf(e, cs, -o * sn);
                acc[i][j + 1] = fmaf(o, cs,  e * sn);
            }
        } else {
            #pragma unroll
            for (int j = 0; j < 8; j++) acc[i][j] += bias[col0 + j];
        }
        float4* out = (float4*)(C + (size_t)r * N + col0);
        out[0] = make_float4(acc[i][0], acc[i][1], acc[i][2], acc[i][3]);
        out[1] = make_float4(acc[i][4], acc[i][5], acc[i][6], acc[i][7]);
    }
}

__global__ void __launch_bounds__(256) gemm_fb_qkv(const float* __restrict__ W,
                                                   const float* __restrict__ b) {
    if (g_flag_q == 0) return;
    gemm_body<N3_, true>(g_xn, W, b, g_qkv);
}
__global__ void __launch_bounds__(256) gemm_fb_out(const float* __restrict__ W,
                                                   const float* __restrict__ b,
                                                   float* __restrict__ out) {
    if (g_flag_o == 0) return;
    gemm_body<D_, false>(g_attn, W, b, out);
}

// ---------------- checks (coalesced, cheap) ----------------------------------------
__global__ void __launch_bounds__(256) check_qkv_kernel(
    const float* __restrict__ W, const float* __restrict__ bias) {
    __shared__ int bad;
    const int tid = threadIdx.x, lane = tid & 31, w = tid >> 5;
    if (tid == 0) bad = 0;
    __syncthreads();
    const int row = (w * 1237 + 11) & (M_ - 1);
    const int c0  = ((w * 677) % (N3_ / 64)) * 64;
    const int ce  = c0 + lane * 2;
    const float* xr = g_xn + (size_t)row * D_;
    float se = 0.f, so = 0.f;
    for (int k = 0; k < D_; k++) {
        const float xv = xr[k];
        se = fmaf(xv, W[(size_t)k * N3_ + ce],     se);
        so = fmaf(xv, W[(size_t)k * N3_ + ce + 1], so);
    }
    se += bias[ce]; so += bias[ce + 1];
    const int t  = row & (T_ - 1);
    const int pi = (ce & (D_ - 1)) >> 1;
    const float sn = g_sin[t * HALF_D + pi], cs = g_cos[t * HALF_D + pi];
    const float re = se * cs - so * sn;
    const float ro = so * cs + se * sn;
    const float ge = g_qkv[(size_t)row * N3_ + ce];
    const float go = g_qkv[(size_t)row * N3_ + ce + 1];
    if (fabsf(ge - re) > 0.01f + 0.003f * fabsf(re) ||
        fabsf(go - ro) > 0.01f + 0.003f * fabsf(ro)) bad = 1;
    __syncthreads();
    if (tid == 0) g_flag_q = bad;
}

__global__ void __launch_bounds__(256) check_out_kernel(
    const float* __restrict__ W, const float* __restrict__ bias,
    const float* __restrict__ out) {
    __shared__ int bad;
    const int tid = threadIdx.x, lane = tid & 31, w = tid >> 5;
    if (tid == 0) bad = 0;
    __syncthreads();
    const int row = (w * 1237 + 17) & (M_ - 1);
    const int c0  = ((w * 677) % (D_ / 64)) * 64;
    const int ce  = c0 + lane * 2;
    const float* ar = g_attn + (size_t)row * D_;
    float se = 0.f, so = 0.f;
    for (int k = 0; k < D_; k++) {
        const float av = ar[k];
        se = fmaf(av, W[(size_t)k * D_ + ce],     se);
        so = fmaf(av, W[(size_t)k * D_ + ce + 1], so);
    }
    se += bias[ce]; so += bias[ce + 1];
    const float ge = out[(size_t)row * D_ + ce];
    const float go = out[(size_t)row * D_ + ce + 1];
    if (fabsf(ge - se) > 0.01f + 0.003f * fabsf(se) ||
        fabsf(go - so) > 0.01f + 0.003f * fabsf(so)) bad = 1;
    __syncthreads();
    if (tid == 0) g_flag_o = bad;
}

// ---------------- attention: reg-score 128-thread kernel (VALIDATED R13) ----------
__global__ void __launch_bounds__(128) attn2_kernel() {
    __shared__ float ks[32][64];
    __shared__ float vs[32][64];

    const int bh = blockIdx.y;
    const int b = bh >> 4, h = bh & 15;
    const int tid = threadIdx.x;
    const int t = blockIdx.x * 128 + tid;
    const int len = g_len[b];

    const float* qrow = g_qkv + (size_t)(b * T_ + t) * N3_ + h * DH_;
    float q[64];
    #pragma unroll
    for (int i = 0; i < 16; i++) {
        float4 v4 = *(const float4*)(qrow + i * 4);
        q[i*4+0] = v4.x; q[i*4+1] = v4.y; q[i*4+2] = v4.z; q[i*4+3] = v4.w;
    }
    float o[64];
    #pragma unroll
    for (int d = 0; d < 64; d++) o[d] = 0.f;
    float m = -1e30f, l = 0.f;

    const float* kbase = g_qkv + (size_t)(b * T_) * N3_ + D_     + h * DH_;
    const float* vbase = g_qkv + (size_t)(b * T_) * N3_ + 2 * D_ + h * DH_;

    for (int s0 = 0; s0 < T_; s0 += 32) {
        if (s0 >= len) break;
        #pragma unroll
        for (int p = 0; p < 4; p++) {
            const int idx = tid + p * 128;
            const int r = idx >> 4, c = (idx & 15) << 2;
            *(float4*)&ks[r][c] = *(const float4*)(kbase + (size_t)(s0 + r) * N3_ + c);
            *(float4*)&vs[r][c] = *(const float4*)(vbase + (size_t)(s0 + r) * N3_ + c);
        }
        __syncthreads();

        const int nv = min(32, len - s0);
        float sc[32];
        float tmax = -1e30f;
        #pragma unroll
        for (int s = 0; s < 32; s++) {
            float acc = 0.f;
            #pragma unroll
            for (int d4 = 0; d4 < 16; d4++) {
                float4 kv = *(const float4*)&ks[s][d4 * 4];
                acc = fmaf(q[d4*4+0], kv.x, acc);
                acc = fmaf(q[d4*4+1], kv.y, acc);
                acc = fmaf(q[d4*4+2], kv.z, acc);
                acc = fmaf(q[d4*4+3], kv.w, acc);
            }
            acc *= 0.125f;
            sc[s] = acc;
            if (s < nv) tmax = fmaxf(tmax, acc);
        }
        const float mnew = fmaxf(m, tmax);
        const float corr = fexp(m - mnew);
        l *= corr;
        #pragma unroll
        for (int d = 0; d < 64; d++) o[d] *= corr;
        #pragma unroll
        for (int s = 0; s < 32; s++) {
            if (s < nv) {
                const float p = fexp(sc[s] - mnew);
                l += p;
                #pragma unroll
                for (int d4 = 0; d4 < 16; d4++) {
                    float4 vv = *(const float4*)&vs[s][d4 * 4];
                    o[d4*4+0] = fmaf(p, vv.x, o[d4*4+0]);
                    o[d4*4+1] = fmaf(p, vv.y, o[d4*4+1]);
                    o[d4*4+2] = fmaf(p, vv.z, o[d4*4+2]);
                    o[d4*4+3] = fmaf(p, vv.w, o[d4*4+3]);
                }
            }
        }
        m = mnew;
        __syncthreads();
    }

    const float invl = 1.f / l;
    float* of = g_attn + (size_t)(b * T_ + t) * D_ + h * DH_;
    #pragma unroll
    for (int i = 0; i < 16; i++)
        *(float4*)(of + i * 4) = make_float4(o[i*4+0]*invl, o[i*4+1]*invl,
                                             o[i*4+2]*invl, o[i*4+3]*invl);
}

// ---------------- launch -----------------------------------------------------------
extern "C" void kernel_launch(void* const* d_in, const int* in_sizes, int n_in,
                              void* d_out, int out_size) {
    const float*        x     = (const float*)d_in[0];
    const unsigned int* mask  = (const unsigned int*)d_in[1];
    const float*        gamma = (const float*)d_in[2];
    const float*        beta  = (const float*)d_in[3];
    const float*        Wqkv  = (const float*)d_in[4];
    const float*        bqkv  = (const float*)d_in[5];
    const float*        Wout  = (const float*)d_in[6];
    const float*        bout  = (const float*)d_in[7];
    float* out = (float*)d_out;

    ln_kernel<<<M_, 256>>>(x, gamma, beta);
    rope_table_kernel<<<(T_ * HALF_D + 255) / 256, 256>>>();
    len_kernel<<<B_, 256>>>(mask);

    // QKV: K16 attempt -> check -> flag-gated frozen fallback
    gemm16<N3_, true><<<dim3(N3_/128, M_/128), 256>>>(g_xn, Wqkv, bqkv, g_qkv);
    check_qkv_kernel<<<1, 256>>>(Wqkv, bqkv);
    gemm_fb_qkv<<<dim3(N3_/128, M_/128), 256>>>(Wqkv, bqkv);

    // attention: validated reg-score kernel, no check
    attn2_kernel<<<dim3(T_/128, B_*H_), 128>>>();

    // out-proj: K16 attempt -> check -> flag-gated frozen fallback
    gemm16<D_, false><<<dim3(D_/128, M_/128), 256>>>(g_attn, Wout, bout, out);
    check_out_kernel<<<1, 256>>>(Wout, bout, out);
    gemm_fb_out<<<dim3(D_/128, M_/128), 256>>>(Wout, bout, out);
}

// round 16
// speedup vs baseline: 2.5565x; 2.5565x over previous
#include <cuda_runtime.h>
#include <math.h>
#include <cstdint>

#define B_  8
#define T_  1024
#define D_  1024
#define H_  16
#define DH_ 64
#define M_  (B_*T_)     // 8192
#define N3_ (3*D_)      // 3072
#define HALF_D 512

// ---------------- scratch -------------------------------------------------------
__device__ __align__(1024) float g_xn[(size_t)M_*D_];
__device__ __align__(1024) float g_qkv[(size_t)M_*N3_];
__device__ __align__(1024) float g_attn[(size_t)M_*D_];
__device__ float g_sin[T_*HALF_D];      // [t][pair]
__device__ float g_cos[T_*HALF_D];
__device__ int   g_len[B_];

// ---------------- fast exp on the FMA pipe, x <= 0 (validated R10/R13) ----------
__device__ __forceinline__ float fexp(float x) {
    x = fmaxf(x, -87.0f);
    const float y = x * 1.4426950408889634f;         // x * log2(e)
    const float n = rintf(y);
    const float t = (y - n) * 0.6931471805599453f;   // |t| <= 0.3466
    float p = fmaf(t, 1.0f/120.0f, 1.0f/24.0f);
    p = fmaf(t, p, 1.0f/6.0f);
    p = fmaf(t, p, 0.5f);
    p = fmaf(t, p, 1.0f);
    p = fmaf(t, p, 1.0f);
    const int e = (int)n;
    return p * __int_as_float((e + 127) << 23);
}

// ---------------- layernorm (round-1 exact) -------------------------------------
__global__ void __launch_bounds__(256) ln_kernel(const float* __restrict__ x,
                                                 const float* __restrict__ gamma,
                                                 const float* __restrict__ beta) {
    __shared__ float ssum[8], ssq[8];
    const int row = blockIdx.x;
    const int tid = threadIdx.x;
    float4 v = *(const float4*)(x + (size_t)row * D_ + tid * 4);
    float s = v.x + v.y + v.z + v.w;
    float q = v.x*v.x + v.y*v.y + v.z*v.z + v.w*v.w;
    #pragma unroll
    for (int o = 16; o > 0; o >>= 1) {
        s += __shfl_down_sync(0xffffffffu, s, o);
        q += __shfl_down_sync(0xffffffffu, q, o);
    }
    if ((tid & 31) == 0) { ssum[tid >> 5] = s; ssq[tid >> 5] = q; }
    __syncthreads();
    float ts = 0.f, tq = 0.f;
    #pragma unroll
    for (int i = 0; i < 8; i++) { ts += ssum[i]; tq += ssq[i]; }
    const float mu  = ts * (1.f / 1024.f);
    const float var = tq * (1.f / 1024.f) - mu * mu;
    const float inv = rsqrtf(var + 1e-5f);
    float4 g  = *(const float4*)(gamma + tid * 4);
    float4 be = *(const float4*)(beta  + tid * 4);
    float4 out;
    out.x = (v.x - mu) * inv * g.x + be.x;
    out.y = (v.y - mu) * inv * g.y + be.y;
    out.z = (v.z - mu) * inv * g.z + be.z;
    out.w = (v.w - mu) * inv * g.w + be.w;
    *(float4*)(g_xn + (size_t)row * D_ + tid * 4) = out;
}

// ---------------- rope tables (round-1 exact) ------------------------------------
__global__ void rope_table_kernel() {
    const int idx = blockIdx.x * blockDim.x + threadIdx.x;
    if (idx >= T_ * HALF_D) return;
    const int t = idx >> 9;
    const int i = idx & (HALF_D - 1);
    const float e   = -(((float)i - 1.0f) * (1.0f / 512.0f));
    const float inv = expf(e * 11.512925464970229f);   // ln(1e5)
    float sn, cs;
    sincosf((float)t * inv, &sn, &cs);
    g_sin[idx] = sn;
    g_cos[idx] = cs;
}

// ---------------- sequence lengths (round-1 exact) --------------------------------
__global__ void len_kernel(const unsigned int* __restrict__ mask) {
    __shared__ int sc[8];
    const int b = blockIdx.x, tid = threadIdx.x;
    int c = 0;
    for (int i = tid; i < T_; i += 256) c += (mask[b * T_ + i] != 0u);
    #pragma unroll
    for (int o = 16; o > 0; o >>= 1) c += __shfl_down_sync(0xffffffffu, c, o);
    if ((tid & 31) == 0) sc[tid >> 5] = c;
    __syncthreads();
    if (tid == 0) {
        int t = 0;
        #pragma unroll
        for (int i = 0; i < 8; i++) t += sc[i];
        g_len[b] = t;
    }
}

// ---------------- SGEMM 128x128x8, 8x8/thread (round-1 exact, FROZEN) -------------
template<int N, bool ROPE>
__device__ __forceinline__ void gemm_body(const float* __restrict__ A,
                                          const float* __restrict__ Bm,
                                          const float* __restrict__ bias,
                                          float* __restrict__ C) {
    __shared__ float As[8][128];
    __shared__ float Bs[8][128];
    const int tid = threadIdx.x;
    const int bm = blockIdx.y, bn = blockIdx.x;
    const int arow = tid >> 1, acol = (tid & 1) << 2;
    const int brow = tid >> 5, bcol = (tid & 31) << 2;
    const int tx = tid & 15, ty = tid >> 4;

    const float* Ap = A + (size_t)(bm * 128 + arow) * 1024 + acol;
    const float* Bp = Bm + (size_t)brow * N + bn * 128 + bcol;

    float acc[8][8];
    #pragma unroll
    for (int i = 0; i < 8; i++)
        #pragma unroll
        for (int j = 0; j < 8; j++) acc[i][j] = 0.f;

    for (int k0 = 0; k0 < 1024; k0 += 8) {
        float4 a4 = *(const float4*)(Ap + k0);
        float4 b4 = *(const float4*)(Bp + (size_t)k0 * N);
        As[acol + 0][arow] = a4.x;
        As[acol + 1][arow] = a4.y;
        As[acol + 2][arow] = a4.z;
        As[acol + 3][arow] = a4.w;
        *(float4*)(&Bs[brow][bcol]) = b4;
        __syncthreads();
        #pragma unroll
        for (int kk = 0; kk < 8; kk++) {
            float4 a0 = *(const float4*)(&As[kk][ty * 8]);
            float4 a1 = *(const float4*)(&As[kk][ty * 8 + 4]);
            float4 b0 = *(const float4*)(&Bs[kk][tx * 8]);
            float4 b1 = *(const float4*)(&Bs[kk][tx * 8 + 4]);
            float ar[8] = {a0.x, a0.y, a0.z, a0.w, a1.x, a1.y, a1.z, a1.w};
            float br[8] = {b0.x, b0.y, b0.z, b0.w, b1.x, b1.y, b1.z, b1.w};
            #pragma unroll
            for (int i = 0; i < 8; i++)
                #pragma unroll
                for (int j = 0; j < 8; j++)
                    acc[i][j] = fmaf(ar[i], br[j], acc[i][j]);
        }
        __syncthreads();
    }

    const int row0 = bm * 128 + ty * 8;
    const int col0 = bn * 128 + tx * 8;
    #pragma unroll
    for (int i = 0; i < 8; i++) {
        const int r = row0 + i;
        if (ROPE) {
            const int t = r & (T_ - 1);
            #pragma unroll
            for (int j = 0; j < 8; j += 2) {
                const int c  = col0 + j;
                const int pi = (c & (D_ - 1)) >> 1;
                const float sn = g_sin[t * HALF_D + pi];
                const float cs = g_cos[t * HALF_D + pi];
                const float e = acc[i][j]     + bias[c];
                const float o = acc[i][j + 1] + bias[c + 1];
                acc[i][j]     = fmaf(e, cs, -o * sn);
                acc[i][j + 1] = fmaf(o, cs,  e * sn);
            }
        } else {
            #pragma unroll
            for (int j = 0; j < 8; j++) acc[i][j] += bias[col0 + j];
        }
        float4* out = (float4*)(C + (size_t)r * N + col0);
        out[0] = make_float4(acc[i][0], acc[i][1], acc[i][2], acc[i][3]);
        out[1] = make_float4(acc[i][4], acc[i][5], acc[i][6], acc[i][7]);
    }
}

__global__ void __launch_bounds__(256) gemm_qkv_kernel(const float* __restrict__ Wqkv,
                                                       const float* __restrict__ bqkv) {
    gemm_body<N3_, true>(g_xn, Wqkv, bqkv, g_qkv);
}
__global__ void __launch_bounds__(256) gemm_out_kernel(const float* __restrict__ Wout,
                                                       const float* __restrict__ bout,
                                                       float* __restrict__ out) {
    gemm_body<D_, false>(g_attn, Wout, bout, out);
}

// ---------------- attention: reg-score 128-thread kernel (VALIDATED R13) ----------
__global__ void __launch_bounds__(128) attn2_kernel() {
    __shared__ float ks[32][64];
    __shared__ float vs[32][64];

    const int bh = blockIdx.y;
    const int b = bh >> 4, h = bh & 15;
    const int tid = threadIdx.x;
    const int t = blockIdx.x * 128 + tid;
    const int len = g_len[b];

    const float* qrow = g_qkv + (size_t)(b * T_ + t) * N3_ + h * DH_;
    float q[64];
    #pragma unroll
    for (int i = 0; i < 16; i++) {
        float4 v4 = *(const float4*)(qrow + i * 4);
        q[i*4+0] = v4.x; q[i*4+1] = v4.y; q[i*4+2] = v4.z; q[i*4+3] = v4.w;
    }
    float o[64];
    #pragma unroll
    for (int d = 0; d < 64; d++) o[d] = 0.f;
    float m = -1e30f, l = 0.f;

    const float* kbase = g_qkv + (size_t)(b * T_) * N3_ + D_     + h * DH_;
    const float* vbase = g_qkv + (size_t)(b * T_) * N3_ + 2 * D_ + h * DH_;

    for (int s0 = 0; s0 < T_; s0 += 32) {
        if (s0 >= len) break;
        #pragma unroll
        for (int p = 0; p < 4; p++) {
            const int idx = tid + p * 128;
            const int r = idx >> 4, c = (idx & 15) << 2;
            *(float4*)&ks[r][c] = *(const float4*)(kbase + (size_t)(s0 + r) * N3_ + c);
            *(float4*)&vs[r][c] = *(const float4*)(vbase + (size_t)(s0 + r) * N3_ + c);
        }
        __syncthreads();

        const int nv = min(32, len - s0);
        float sc[32];
        float tmax = -1e30f;
        #pragma unroll
        for (int s = 0; s < 32; s++) {
            float acc = 0.f;
            #pragma unroll
            for (int d4 = 0; d4 < 16; d4++) {
                float4 kv = *(const float4*)&ks[s][d4 * 4];
                acc = fmaf(q[d4*4+0], kv.x, acc);
                acc = fmaf(q[d4*4+1], kv.y, acc);
                acc = fmaf(q[d4*4+2], kv.z, acc);
                acc = fmaf(q[d4*4+3], kv.w, acc);
            }
            acc *= 0.125f;
            sc[s] = acc;
            if (s < nv) tmax = fmaxf(tmax, acc);
        }
        const float mnew = fmaxf(m, tmax);
        const float corr = fexp(m - mnew);
        l *= corr;
        #pragma unroll
        for (int d = 0; d < 64; d++) o[d] *= corr;
        #pragma unroll
        for (int s = 0; s < 32; s++) {
            if (s < nv) {
                const float p = fexp(sc[s] - mnew);
                l += p;
                #pragma unroll
                for (int d4 = 0; d4 < 16; d4++) {
                    float4 vv = *(const float4*)&vs[s][d4 * 4];
                    o[d4*4+0] = fmaf(p, vv.x, o[d4*4+0]);
                    o[d4*4+1] = fmaf(p, vv.y, o[d4*4+1]);
                    o[d4*4+2] = fmaf(p, vv.z, o[d4*4+2]);
                    o[d4*4+3] = fmaf(p, vv.w, o[d4*4+3]);
                }
            }
        }
        m = mnew;
        __syncthreads();
    }

    const float invl = 1.f / l;
    float* of = g_attn + (size_t)(b * T_ + t) * D_ + h * DH_;
    #pragma unroll
    for (int i = 0; i < 16; i++)
        *(float4*)(of + i * 4) = make_float4(o[i*4+0]*invl, o[i*4+1]*invl,
                                             o[i*4+2]*invl, o[i*4+3]*invl);
}

// ---------------- launch -----------------------------------------------------------
extern "C" void kernel_launch(void* const* d_in, const int* in_sizes, int n_in,
                              void* d_out, int out_size) {
    const float*        x     = (const float*)d_in[0];
    const unsigned int* mask  = (const unsigned int*)d_in[1];
    const float*        gamma = (const float*)d_in[2];
    const float*        beta  = (const float*)d_in[3];
    const float*        Wqkv  = (const float*)d_in[4];
    const float*        bqkv  = (const float*)d_in[5];
    const float*        Wout  = (const float*)d_in[6];
    const float*        bout  = (const float*)d_in[7];
    float* out = (float*)d_out;

    ln_kernel<<<M_, 256>>>(x, gamma, beta);
    rope_table_kernel<<<(T_ * HALF_D + 255) / 256, 256>>>();
    len_kernel<<<B_, 256>>>(mask);

    // QKV: frozen round-1 kernel
    gemm_qkv_kernel<<<dim3(N3_/128, M_/128), 256>>>(Wqkv, bqkv);

    // attention: validated reg-score fexp kernel
    attn2_kernel<<<dim3(T_/128, B_*H_), 128>>>();

    // out-proj: frozen round-1 kernel
    gemm_out_kernel<<<dim3(D_/128, M_/128), 256>>>(Wout, bout, out);
}